// round 7
// baseline (speedup 1.0000x reference)
#include <cuda_runtime.h>

#define BB 4
#define PP 2048
#define EE 1024
#define HH 16
#define HD 64
#define NBIN 256
#define NPART 8
#define NVP 32

// Scratch (fully overwritten every launch)
__device__ __align__(16) float g_Qs[BB*HH*PP];      // [b][h][p]
__device__ __align__(16) float g_Ks[BB*HH*PP];      // [b][h][p]
__device__ __align__(16) float g_Vpart[BB*NVP*EE];
__device__ __align__(16) float g_U[BB*HH*EE];       // [b][h][n]
__device__ __align__(16) float g_diag[BB*HH*PP];    // [b][h][p]
__device__ __align__(16) float g_bt[BB*HH*NPART*5*NBIN];
__device__ __align__(8)  float2 g_mnmx[BB*HH];

__device__ __forceinline__ float ex2f(float x){
    float y; asm("ex2.approx.ftz.f32 %0, %1;" : "=f"(y) : "f"(x)); return y;
}
__device__ __forceinline__ unsigned long long pk2(float lo, float hi){
    unsigned long long r; asm("mov.b64 %0, {%1,%2};" : "=l"(r) : "f"(lo), "f"(hi)); return r;
}
__device__ __forceinline__ void upk2(unsigned long long v, float& lo, float& hi){
    asm("mov.b64 {%0,%1}, %2;" : "=f"(lo), "=f"(hi) : "l"(v));
}
__device__ __forceinline__ unsigned long long fma2(unsigned long long a,
                                                  unsigned long long b,
                                                  unsigned long long c){
    unsigned long long d;
    asm("fma.rn.f32x2 %0, %1, %2, %3;" : "=l"(d) : "l"(a), "l"(b), "l"(c));
    return d;
}
__device__ __forceinline__ unsigned long long mul2(unsigned long long a,
                                                  unsigned long long b){
    unsigned long long d;
    asm("mul.rn.f32x2 %0, %1, %2;" : "=l"(d) : "l"(a), "l"(b));
    return d;
}

// ---------------------------------------------------------------------------
// K1: Qs/Ks head row-sums (coalesced writes) + V partial column sums.
//   blocks [0,8192): Q, [8192,16384): K, [16384,16896): V.
//   Q/K block = (bh, ptile): 16 consecutive p of one (b,h); smem-staged
//   64B coalesced store (kills dirty-sector write amplification).
// ---------------------------------------------------------------------------
__global__ void k_reduce(const float* __restrict__ Q, const float* __restrict__ K,
                         const float* __restrict__ V) {
    int bid = blockIdx.x;
    int tid = threadIdx.x;
    if (bid < 16384) {
        const float* src; float* dst; int base;
        if (bid < 8192) { src = Q; dst = g_Qs; base = bid; }
        else            { src = K; dst = g_Ks; base = bid - 8192; }
        int bh = base >> 7;        // 64
        int ptile = base & 127;    // 128 tiles of 16 p
        int b = bh >> 4, h = bh & 15;
        int p = ptile * 16 + (tid >> 4);
        int lane16 = tid & 15;
        float4 v = ((const float4*)(src + (((size_t)(b * PP + p)) << 10) + h * HD))[lane16];
        float s = (v.x + v.y) + (v.z + v.w);
        s += __shfl_down_sync(0xffffffffu, s, 8, 16);
        s += __shfl_down_sync(0xffffffffu, s, 4, 16);
        s += __shfl_down_sync(0xffffffffu, s, 2, 16);
        s += __shfl_down_sync(0xffffffffu, s, 1, 16);
        __shared__ float sm[16];
        if (lane16 == 0) sm[tid >> 4] = s;
        __syncthreads();
        if (tid < 16) dst[(bh << 11) + ptile * 16 + tid] = sm[tid];
    } else {
        int blk = bid - 16384;
        int b = blk >> 7, r = blk & 127, pc = r >> 2, cg = r & 3;
        int c = cg * 256 + tid;
        const float* base = V + ((size_t)b * PP + pc * 64) * EE + c;
        float s = 0.f;
        #pragma unroll 16
        for (int p = 0; p < 64; p++) s += base[(size_t)p * EE];
        g_Vpart[(b * NVP + pc) * EE + c] = s;
    }
}

// ---------------------------------------------------------------------------
// min/max of ks[2048] for one bh, exact. 256 threads.
// ---------------------------------------------------------------------------
__device__ __forceinline__ void ks_minmax(const float4* kr4, int tid,
                                          float* s_mn, float* s_mx) {
    __shared__ float rmn[8], rmx[8];
    float mn = 3.4e38f, mx = -3.4e38f;
    #pragma unroll
    for (int i = 0; i < 2; i++) {
        float4 v = kr4[i * 256 + tid];
        mn = fminf(mn, fminf(fminf(v.x, v.y), fminf(v.z, v.w)));
        mx = fmaxf(mx, fmaxf(fmaxf(v.x, v.y), fmaxf(v.z, v.w)));
    }
    #pragma unroll
    for (int off = 16; off; off >>= 1) {
        mn = fminf(mn, __shfl_xor_sync(0xffffffffu, mn, off));
        mx = fmaxf(mx, __shfl_xor_sync(0xffffffffu, mx, off));
    }
    if ((tid & 31) == 0) { rmn[tid >> 5] = mn; rmx[tid >> 5] = mx; }
    __syncthreads();
    if (tid == 0) {
        float a = rmn[0], c = rmx[0];
        #pragma unroll
        for (int w = 1; w < 8; w++) { a = fminf(a, rmn[w]); c = fmaxf(c, rmx[w]); }
        *s_mn = a; *s_mx = c;
    }
    __syncthreads();
}

// ---------------------------------------------------------------------------
// K_mid: blocks [0,512) = bin tables; [512,576) = proj_u -> g_U[b][h][n].
// ---------------------------------------------------------------------------
__global__ void k_mid(const float* __restrict__ W) {
    int bid = blockIdx.x;
    int tid = threadIdx.x;
    if (bid < 512) {
        int bh = bid >> 3, part = bid & 7;
        __shared__ float s_mn, s_mx;
        __shared__ float tb[5][NBIN];
        const float4* kr4 = (const float4*)(g_Ks + ((size_t)bh << 11));
        ks_minmax(kr4, tid, &s_mn, &s_mx);
        #pragma unroll
        for (int c = 0; c < 5; c++) tb[c][tid] = 0.f;
        __syncthreads();

        float mn = s_mn, mx = s_mx;
        float w = fmaxf(mx - mn, 1e-20f) * (1.0f / NBIN);
        float invw = 1.0f / w;

        float k = g_Ks[((size_t)bh << 11) + (part << 8) + tid];
        int idx = (int)((k - mn) * invw);
        idx = max(0, min(NBIN - 1, idx));
        float kb = mn + ((float)idx + 0.5f) * w;
        float d  = k - kb;
        float d2 = d * d;
        atomicAdd(&tb[0][idx], 1.0f);
        atomicAdd(&tb[1][idx], d);
        atomicAdd(&tb[2][idx], 0.5f * d2);
        atomicAdd(&tb[3][idx], d * d2 * (1.0f / 6.0f));
        atomicAdd(&tb[4][idx], d2 * d2 * (1.0f / 24.0f));
        __syncthreads();

        float* out = g_bt + (size_t)((bh * NPART + part) * 5) * NBIN;
        #pragma unroll
        for (int c = 0; c < 5; c++) out[c * NBIN + tid] = tb[c][tid];
        if (part == 0 && tid == 0) g_mnmx[bh] = make_float2(mn, mx);
    } else {
        int blk = bid - 512;
        int b = blk >> 4, h = blk & 15;
        __shared__ float vs[HD];
        if (tid < HD) {
            float s = 0.f;
            #pragma unroll
            for (int pc = 0; pc < NVP; pc++)
                s += g_Vpart[(b * NVP + pc) * EE + h * HD + tid];
            vs[tid] = s;
        }
        __syncthreads();
        for (int n = tid; n < EE; n += 256) {
            const float4* wr = (const float4*)(W + (size_t)n * EE + h * HD);
            float acc = 0.f;
            #pragma unroll
            for (int e = 0; e < 16; e++) {
                float4 w = wr[e];
                acc += w.x * vs[4*e] + w.y * vs[4*e+1] + w.z * vs[4*e+2] + w.w * vs[4*e+3];
            }
            g_U[((b * HH + h) << 10) + n] = acc;   // coalesced
        }
    }
}

// ---------------------------------------------------------------------------
// K3: softmax diagonal, binned moments, paired bins in f32x2.
//   grid 512 = 64bh x 8 chunks of 256 queries; 256 threads.
//   Pair layout: cfA[pr]=(c1e,c1o,c2e,c2o), cfB[pr]=(c3e,c3o,c4e,c4o),
//                cfC[pr]=(c0e,c0o).
// ---------------------------------------------------------------------------
__global__ void __launch_bounds__(256) k_softmax_diag() {
    int bh = blockIdx.x >> 3, ic = blockIdx.x & 7;
    int tid = threadIdx.x;
    __shared__ __align__(16) float4 cfA[NBIN/2];
    __shared__ __align__(16) float4 cfB[NBIN/2];
    __shared__ __align__(8)  float2 cfC[NBIN/2];
    __shared__ float2 s_mm;
    if (tid == 0) s_mm = g_mnmx[bh];

    // each thread sums one bin's 5 coefs over 8 parts, writes into pair slots
    {
        int bin = tid;
        const float* bt = g_bt + (size_t)(bh * NPART * 5) * NBIN + bin;
        float c0 = 0, c1 = 0, c2 = 0, c3 = 0, c4 = 0;
        #pragma unroll
        for (int part = 0; part < NPART; part++) {
            const float* p = bt + (size_t)(part * 5) * NBIN;
            c0 += p[0];
            c1 += p[NBIN];
            c2 += p[2 * NBIN];
            c3 += p[3 * NBIN];
            c4 += p[4 * NBIN];
        }
        int pr = bin >> 1, od = bin & 1;
        float* A = (float*)&cfA[pr];
        float* Bv = (float*)&cfB[pr];
        float* Cv = (float*)&cfC[pr];
        A[od] = c1; A[2 + od] = c2;
        Bv[od] = c3; Bv[2 + od] = c4;
        Cv[od] = c0;
    }
    __syncthreads();

    float mn = s_mm.x, mx = s_mm.y;
    float w = fmaxf(mx - mn, 1e-20f) * (1.0f / NBIN);

    const float L2E = 1.44269504088896340736f;
    int i = (ic << 8) + tid;
    float a  = 0.125f * g_Qs[((size_t)bh << 11) + i];
    float a2 = a * L2E;
    float nM = -((a2 >= 0.f) ? a2 * mx : a2 * mn);
    float rd  = ex2f(a2 * w);
    float rd2 = rd * rd;
    unsigned long long aa  = pk2(a, a);
    unsigned long long rdp = pk2(rd2, rd2);

    unsigned long long acc2 = pk2(0.f, 0.f);
    #pragma unroll 1
    for (int seg = 0; seg < 8; seg++) {
        float kb = fmaf((float)(seg * 32) + 0.5f, w, mn);
        float e0 = ex2f(fmaf(a2, kb, nM));
        unsigned long long e2 = pk2(e0, e0 * rd);
        #pragma unroll
        for (int t = 0; t < 16; t++) {
            int pr = seg * 16 + t;
            float4 A = cfA[pr];
            float4 Bv = cfB[pr];
            float2 Cv = cfC[pr];
            unsigned long long p = fma2(aa, pk2(Bv.z, Bv.w), pk2(Bv.x, Bv.y));
            p = fma2(aa, p, pk2(A.z, A.w));
            p = fma2(aa, p, pk2(A.x, A.y));
            p = fma2(aa, p, pk2(Cv.x, Cv.y));
            acc2 = fma2(e2, p, acc2);
            e2 = mul2(e2, rdp);
        }
    }
    float dlo, dhi; upk2(acc2, dlo, dhi);
    float denom = dlo + dhi;

    float ki  = g_Ks[((size_t)bh << 11) + i];
    float num = ex2f(fmaf(a2, ki, nM));
    g_diag[((size_t)bh << 11) + i] = num / denom;
}

// ---------------------------------------------------------------------------
// K4: Y[b,p,n] = sum_h diag[b,h,p]*U[b,h,n] + bias[n].
//   smem-tiled: 32p x 256n per block; thread = 4p x 8n in f32x2 accumulators.
//   grid 1024 = 4b x 64pt x 4nt; 256 threads.
// ---------------------------------------------------------------------------
__global__ void __launch_bounds__(256) k_out(const float* __restrict__ bias,
                                             float* __restrict__ Y) {
    int nt = blockIdx.x & 3;
    int pt = (blockIdx.x >> 2) & 63;
    int b  = blockIdx.x >> 8;
    int tid = threadIdx.x;

    __shared__ __align__(16) float u_s[HH][256];
    __shared__ __align__(16) float d_s[HH][32];

    // load U tile: 16h x 256n = 1024 float4
    #pragma unroll
    for (int r = 0; r < 4; r++) {
        int idx = r * 256 + tid;
        int h = idx >> 6, q = idx & 63;
        ((float4*)u_s[h])[q] =
            ((const float4*)(g_U + ((b * HH + h) << 10) + nt * 256))[q];
    }
    // load diag tile: 16h x 32p = 128 float4
    if (tid < 128) {
        int h = tid >> 3, q = tid & 7;
        ((float4*)d_s[h])[q] =
            ((const float4*)(g_diag + (((size_t)(b * HH + h)) << 11) + pt * 32))[q];
    }
    __syncthreads();

    int pq = tid >> 5;          // 8 p-groups of 4
    int nq = tid & 31;          // 32 n-groups of 8
    int nblk = nt * 256 + nq * 8;

    float4 b0 = *(const float4*)(bias + nblk);
    float4 b1 = *(const float4*)(bias + nblk + 4);
    unsigned long long binit[4] = { pk2(b0.x, b0.y), pk2(b0.z, b0.w),
                                    pk2(b1.x, b1.y), pk2(b1.z, b1.w) };
    unsigned long long acc[4][4];
    #pragma unroll
    for (int p = 0; p < 4; p++)
        #pragma unroll
        for (int j = 0; j < 4; j++) acc[p][j] = binit[j];

    #pragma unroll
    for (int h = 0; h < HH; h++) {
        float4 u01 = ((const float4*)u_s[h])[nq * 2];
        float4 u23 = ((const float4*)u_s[h])[nq * 2 + 1];
        float4 d   = *(const float4*)&d_s[h][pq * 4];
        unsigned long long up[4] = { pk2(u01.x, u01.y), pk2(u01.z, u01.w),
                                     pk2(u23.x, u23.y), pk2(u23.z, u23.w) };
        unsigned long long dp[4] = { pk2(d.x, d.x), pk2(d.y, d.y),
                                     pk2(d.z, d.z), pk2(d.w, d.w) };
        #pragma unroll
        for (int p = 0; p < 4; p++)
            #pragma unroll
            for (int j = 0; j < 4; j++)
                acc[p][j] = fma2(dp[p], up[j], acc[p][j]);
    }

    #pragma unroll
    for (int p = 0; p < 4; p++) {
        float f[8];
        #pragma unroll
        for (int j = 0; j < 4; j++) upk2(acc[p][j], f[2*j], f[2*j+1]);
        float* yrow = Y + (((size_t)(b * PP + pt * 32 + pq * 4 + p)) << 10) + nblk;
        ((float4*)yrow)[0] = make_float4(f[0], f[1], f[2], f[3]);
        ((float4*)yrow)[1] = make_float4(f[4], f[5], f[6], f[7]);
    }
}

extern "C" void kernel_launch(void* const* d_in, const int* in_sizes, int n_in,
                              void* d_out, int out_size) {
    const float* Q    = (const float*)d_in[0];
    const float* K    = (const float*)d_in[1];
    const float* V    = (const float*)d_in[2];
    const float* W    = (const float*)d_in[3];
    const float* bias = (const float*)d_in[4];
    float* Y = (float*)d_out;

    k_reduce<<<16896, 256>>>(Q, K, V);
    k_mid<<<576, 256>>>(W);
    k_softmax_diag<<<512, 256>>>();
    k_out<<<1024, 256>>>(bias, Y);
}

// round 9
// speedup vs baseline: 1.3359x; 1.3359x over previous
#include <cuda_runtime.h>

#define BB 4
#define PP 2048
#define EE 1024
#define HH 16
#define HD 64
#define NB2 64          // bins
#define NC 11           // Taylor coefs c0..c10
#define NPART 8
#define NVP 32

// Scratch (fully overwritten every launch)
__device__ __align__(16) float g_Qs[BB*HH*PP];
__device__ __align__(16) float g_Ks[BB*HH*PP];
__device__ __align__(16) float g_Vpart[BB*NVP*EE];
__device__ __align__(16) float g_U[BB*HH*EE];       // [b][h][n]
__device__ __align__(16) float g_diag[BB*HH*PP];
__device__ __align__(16) float g_bt[BB*HH*NPART*NC*NB2];
__device__ __align__(8)  float2 g_mnmx[BB*HH];

__device__ __forceinline__ float ex2f(float x){
    float y; asm("ex2.approx.ftz.f32 %0, %1;" : "=f"(y) : "f"(x)); return y;
}

// ---------------------------------------------------------------------------
// K1: blocks [0,512): V partial column sums (long-running — scheduled FIRST
//     so they overlap the Q/K stream). [512,8704): Q/K head row-sums, 2 rows
//     per thread (MLP=2), smem-staged 128B coalesced stores.
// ---------------------------------------------------------------------------
__global__ void k_reduce(const float* __restrict__ Q, const float* __restrict__ K,
                         const float* __restrict__ V) {
    int bid = blockIdx.x;
    int tid = threadIdx.x;
    if (bid < 512) {
        int b = bid >> 7, r = bid & 127, pc = r >> 2, cg = r & 3;
        int c = cg * 256 + tid;
        const float* base = V + ((size_t)b * PP + pc * 64) * EE + c;
        float s = 0.f;
        #pragma unroll 16
        for (int p = 0; p < 64; p++) s += base[(size_t)p * EE];
        g_Vpart[(b * NVP + pc) * EE + c] = s;
    } else {
        int base = bid - 512;                 // 0..8191
        const float* src; float* dst;
        if (base < 4096) { src = Q; dst = g_Qs; }
        else             { src = K; dst = g_Ks; base -= 4096; }
        int bh = base >> 6;                   // 64
        int ptile = base & 63;                // 64 tiles of 32 p
        int b = bh >> 4, h = bh & 15;
        int seg = tid >> 4, lane16 = tid & 15;
        int p0 = ptile * 32 + seg;
        const float4* r0 = (const float4*)(src + (((size_t)(b * PP + p0)) << 10) + h * HD);
        const float4* r1 = (const float4*)(src + (((size_t)(b * PP + p0 + 16)) << 10) + h * HD);
        float4 v0 = r0[lane16];
        float4 v1 = r1[lane16];
        float s0 = (v0.x + v0.y) + (v0.z + v0.w);
        float s1 = (v1.x + v1.y) + (v1.z + v1.w);
        #pragma unroll
        for (int off = 8; off; off >>= 1) {
            s0 += __shfl_down_sync(0xffffffffu, s0, off, 16);
            s1 += __shfl_down_sync(0xffffffffu, s1, off, 16);
        }
        __shared__ float sm[32];
        if (lane16 == 0) { sm[seg] = s0; sm[16 + seg] = s1; }
        __syncthreads();
        if (tid < 32) dst[(bh << 11) + ptile * 32 + tid] = sm[tid];
    }
}

// ---------------------------------------------------------------------------
// min/max of ks[2048] for one bh, exact. 256 threads.
// ---------------------------------------------------------------------------
__device__ __forceinline__ void ks_minmax(const float4* kr4, int tid,
                                          float* s_mn, float* s_mx) {
    __shared__ float rmn[8], rmx[8];
    float mn = 3.4e38f, mx = -3.4e38f;
    #pragma unroll
    for (int i = 0; i < 2; i++) {
        float4 v = kr4[i * 256 + tid];
        mn = fminf(mn, fminf(fminf(v.x, v.y), fminf(v.z, v.w)));
        mx = fmaxf(mx, fmaxf(fmaxf(v.x, v.y), fmaxf(v.z, v.w)));
    }
    #pragma unroll
    for (int off = 16; off; off >>= 1) {
        mn = fminf(mn, __shfl_xor_sync(0xffffffffu, mn, off));
        mx = fmaxf(mx, __shfl_xor_sync(0xffffffffu, mx, off));
    }
    if ((tid & 31) == 0) { rmn[tid >> 5] = mn; rmx[tid >> 5] = mx; }
    __syncthreads();
    if (tid == 0) {
        float a = rmn[0], c = rmx[0];
        #pragma unroll
        for (int w = 1; w < 8; w++) { a = fminf(a, rmn[w]); c = fmaxf(c, rmx[w]); }
        *s_mn = a; *s_mx = c;
    }
    __syncthreads();
}

// ---------------------------------------------------------------------------
// K_mid: blocks [0,512): bin tables (64bh x 8 parts): 64 bins x 11 Taylor
//   moments c_k = Sum d^k/k!. blocks [512,768): proj_u (b,h,nchunk).
// ---------------------------------------------------------------------------
__global__ void k_mid(const float* __restrict__ W) {
    int bid = blockIdx.x;
    int tid = threadIdx.x;
    if (bid < 512) {
        int bh = bid >> 3, part = bid & 7;
        __shared__ float s_mn, s_mx;
        __shared__ float tb[NC][NB2];
        const float4* kr4 = (const float4*)(g_Ks + ((size_t)bh << 11));
        ks_minmax(kr4, tid, &s_mn, &s_mx);
        for (int i = tid; i < NC * NB2; i += 256) ((float*)tb)[i] = 0.f;
        __syncthreads();

        float mn = s_mn, mx = s_mx;
        float w = fmaxf(mx - mn, 1e-20f) * (1.0f / NB2);
        float invw = 1.0f / w;

        float k = g_Ks[((size_t)bh << 11) + (part << 8) + tid];
        int idx = (int)((k - mn) * invw);
        idx = max(0, min(NB2 - 1, idx));
        float kb = mn + ((float)idx + 0.5f) * w;
        float d  = k - kb;
        float t = 1.0f;
        atomicAdd(&tb[0][idx], 1.0f);
        const float rc[10] = {1.f, 0.5f, 1.f/3.f, 0.25f, 0.2f, 1.f/6.f,
                              1.f/7.f, 0.125f, 1.f/9.f, 0.1f};
        #pragma unroll
        for (int c = 1; c <= 10; c++) {
            t *= d * rc[c - 1];
            atomicAdd(&tb[c][idx], t);
        }
        __syncthreads();

        float* out = g_bt + (size_t)((bh * NPART + part) * NC) * NB2;
        for (int i = tid; i < NC * NB2; i += 256) out[i] = ((float*)tb)[i];
        if (part == 0 && tid == 0) g_mnmx[bh] = make_float2(mn, mx);
    } else {
        int blk = bid - 512;                 // 0..255
        int b = blk >> 6, h = (blk >> 2) & 15, nc = blk & 3;
        __shared__ float vs[HD];
        if (tid < HD) {
            float s = 0.f;
            #pragma unroll
            for (int pc = 0; pc < NVP; pc++)
                s += g_Vpart[(b * NVP + pc) * EE + h * HD + tid];
            vs[tid] = s;
        }
        __syncthreads();
        int n = nc * 256 + tid;
        const float4* wr = (const float4*)(W + (size_t)n * EE + h * HD);
        float acc = 0.f;
        #pragma unroll
        for (int e = 0; e < 16; e++) {
            float4 w4 = wr[e];
            acc += w4.x * vs[4*e] + w4.y * vs[4*e+1] + w4.z * vs[4*e+2] + w4.w * vs[4*e+3];
        }
        g_U[((b * HH + h) << 10) + n] = acc;
    }
}

// ---------------------------------------------------------------------------
// K3: softmax diagonal: 64 bins x degree-10 Taylor, geometric e-recurrence
//   with ex2 restart every 16 bins. grid 512 = 64bh x 8 chunks; 256 threads.
//   cf[bin] = 12 floats (c0..c10 + pad) -> 3 LDS.128 broadcasts per bin.
// ---------------------------------------------------------------------------
__global__ void __launch_bounds__(256) k_softmax_diag() {
    int bh = blockIdx.x >> 3, ic = blockIdx.x & 7;
    int tid = threadIdx.x;
    __shared__ __align__(16) float cf[NB2][12];
    __shared__ float2 s_mm;
    if (tid == 0) s_mm = g_mnmx[bh];

    // sum 8 partial tables: 704 entries over 256 threads
    {
        const float* bt = g_bt + (size_t)(bh * NPART * NC) * NB2;
        for (int i = tid; i < NC * NB2; i += 256) {
            int c = i >> 6, bin = i & 63;
            float s = 0.f;
            #pragma unroll
            for (int part = 0; part < NPART; part++)
                s += bt[(size_t)(part * NC) * NB2 + i];
            cf[bin][c] = s;
        }
        for (int i = tid; i < NB2; i += 256) cf[i][11] = 0.f;
    }
    __syncthreads();

    float mn = s_mm.x, mx = s_mm.y;
    float w = fmaxf(mx - mn, 1e-20f) * (1.0f / NB2);

    const float L2E = 1.44269504088896340736f;
    int i = (ic << 8) + tid;
    float a  = 0.125f * g_Qs[((size_t)bh << 11) + i];
    float a2 = a * L2E;
    float nM = -((a2 >= 0.f) ? a2 * mx : a2 * mn);
    float rd = ex2f(a2 * w);

    float acc0 = 0.f, acc1 = 0.f;
    #pragma unroll 1
    for (int seg = 0; seg < 4; seg++) {
        float kb = fmaf((float)(seg * 16) + 0.5f, w, mn);
        float e  = ex2f(fmaf(a2, kb, nM));
        float accs = 0.f;
        #pragma unroll
        for (int t = 0; t < 16; t++) {
            int bin = seg * 16 + t;
            float4 A = *(const float4*)&cf[bin][0];   // c0..c3
            float4 B = *(const float4*)&cf[bin][4];   // c4..c7
            float4 C = *(const float4*)&cf[bin][8];   // c8,c9,c10,pad
            float p = C.z;
            p = fmaf(a, p, C.y);
            p = fmaf(a, p, C.x);
            p = fmaf(a, p, B.w);
            p = fmaf(a, p, B.z);
            p = fmaf(a, p, B.y);
            p = fmaf(a, p, B.x);
            p = fmaf(a, p, A.w);
            p = fmaf(a, p, A.z);
            p = fmaf(a, p, A.y);
            p = fmaf(a, p, A.x);
            accs = fmaf(e, p, accs);
            e *= rd;
        }
        if (seg & 1) acc1 += accs; else acc0 += accs;
    }
    float denom = acc0 + acc1;

    float ki  = g_Ks[((size_t)bh << 11) + i];
    float num = ex2f(fmaf(a2, ki, nM));
    g_diag[((size_t)bh << 11) + i] = num / denom;
}

// ---------------------------------------------------------------------------
// K4: Y[b,p,n] = sum_h diag[b,h,p]*U[b,h,n] + bias[n].  Scalar.
//   32p x 256n tile; thread = 4p x 8n (32 acc regs), u/d via LDS.128
//   (d is warp-broadcast). ~55 regs -> 8 blocks/SM. grid 1024, 256 thr.
// ---------------------------------------------------------------------------
__global__ void __launch_bounds__(256) k_out(const float* __restrict__ bias,
                                             float* __restrict__ Y) {
    int nt = blockIdx.x & 3;
    int pt = (blockIdx.x >> 2) & 63;
    int b  = blockIdx.x >> 8;
    int tid = threadIdx.x;

    __shared__ __align__(16) float u_s[HH][256];
    __shared__ __align__(16) float d_s[HH][32];

    #pragma unroll
    for (int r = 0; r < 4; r++) {
        int idx = r * 256 + tid;
        int h = idx >> 6, q = idx & 63;
        ((float4*)u_s[h])[q] =
            ((const float4*)(g_U + ((b * HH + h) << 10) + nt * 256))[q];
    }
    if (tid < 128) {
        int h = tid >> 3, q = tid & 7;
        ((float4*)d_s[h])[q] =
            ((const float4*)(g_diag + (((size_t)(b * HH + h)) << 11) + pt * 32))[q];
    }
    __syncthreads();

    int pq = tid >> 5;          // warp index = p-group of 4
    int nq = tid & 31;          // n-group of 8
    int nblk = nt * 256 + nq * 8;

    float4 b0 = *(const float4*)(bias + nblk);
    float4 b1 = *(const float4*)(bias + nblk + 4);
    float acc[4][8];
    #pragma unroll
    for (int p = 0; p < 4; p++) {
        acc[p][0] = b0.x; acc[p][1] = b0.y; acc[p][2] = b0.z; acc[p][3] = b0.w;
        acc[p][4] = b1.x; acc[p][5] = b1.y; acc[p][6] = b1.z; acc[p][7] = b1.w;
    }

    #pragma unroll
    for (int h = 0; h < HH; h++) {
        float4 d   = *(const float4*)&d_s[h][pq * 4];          // broadcast
        float4 u01 = ((const float4*)u_s[h])[nq * 2];
        float4 u23 = ((const float4*)u_s[h])[nq * 2 + 1];
        float u[8] = {u01.x, u01.y, u01.z, u01.w, u23.x, u23.y, u23.z, u23.w};
        float dp[4] = {d.x, d.y, d.z, d.w};
        #pragma unroll
        for (int p = 0; p < 4; p++)
            #pragma unroll
            for (int j = 0; j < 8; j++)
                acc[p][j] = fmaf(dp[p], u[j], acc[p][j]);
    }

    #pragma unroll
    for (int p = 0; p < 4; p++) {
        float* yrow = Y + (((size_t)(b * PP + pt * 32 + pq * 4 + p)) << 10) + nblk;
        ((float4*)yrow)[0] = make_float4(acc[p][0], acc[p][1], acc[p][2], acc[p][3]);
        ((float4*)yrow)[1] = make_float4(acc[p][4], acc[p][5], acc[p][6], acc[p][7]);
    }
}

extern "C" void kernel_launch(void* const* d_in, const int* in_sizes, int n_in,
                              void* d_out, int out_size) {
    const float* Q    = (const float*)d_in[0];
    const float* K    = (const float*)d_in[1];
    const float* V    = (const float*)d_in[2];
    const float* W    = (const float*)d_in[3];
    const float* bias = (const float*)d_in[4];
    float* Y = (float*)d_out;

    k_reduce<<<8704, 256>>>(Q, K, V);
    k_mid<<<768, 256>>>(W);
    k_softmax_diag<<<512, 256>>>();
    k_out<<<1024, 256>>>(bias, Y);
}